// round 9
// baseline (speedup 1.0000x reference)
#include <cuda_runtime.h>
#include <cuda_bf16.h>
#include <cuda_fp16.h>
#include <cstdint>
#include <cstddef>

#define DEV_INLINE __device__ __forceinline__

// ---------------- problem dims (fixed) ----------------
#define BATCH_M 8192   // 2*4096 rows of x
#define DIM_K   4096
#define DIM_N   4096

// ---------------- scratch (static device arrays; no cudaMalloc) ----------
// quantized values stored as f16 (e4m3 grid is exactly representable in f16)
__device__ __align__(16) __half g_qx_h[(size_t)BATCH_M * DIM_K]; // 64 MB
__device__ __align__(16) __half g_qw_h[(size_t)DIM_N * DIM_K];   // 32 MB
__device__ unsigned int g_amax_bits[2];   // [0]=x, [1]=w
__device__ unsigned int g_lo16_or;        // OR of low-16 bits of x fp32 words; 0 => x/out are fp32

// ---------------- helpers ----------------
// quantize a float pair to e4m3 (RN, satfinite) and return the exact values as f16x2
DEV_INLINE uint32_t qpair_h2(float lo, float hi) {
    uint16_t e;
    asm("cvt.rn.satfinite.e4m3x2.f32 %0, %1, %2;" : "=h"(e) : "f"(hi), "f"(lo));
    uint32_t h;
    asm("cvt.rn.f16x2.e4m3x2 %0, %1;" : "=r"(h) : "h"(e));
    return h;
}

// ---------------- reset ----------------
__global__ void init_kernel() {
    if (threadIdx.x == 0) {
        g_amax_bits[0] = 0u; g_amax_bits[1] = 0u; g_lo16_or = 0u;
    }
}

// ---------------- dtype probe: are x's fp32 words bf16-upcasts? ----------------
// If x is a float32 buffer holding upcast bf16 values, every word's low 16 bits are 0.
// If x is a bf16 buffer, fp32-word low halves are bf16 elements (generically nonzero).
__global__ void probe_kernel(const unsigned int* __restrict__ xw) {
    unsigned int v = 0;
    // sample 64 strided regions of 256 words each (all within the smaller bf16 buffer size)
    const size_t stride = (size_t)65536;
    for (int r = 0; r < 64; r++) {
        v |= xw[r * stride + threadIdx.x] & 0xFFFFu;
    }
    #pragma unroll
    for (int o = 16; o > 0; o >>= 1) v |= __shfl_xor_sync(0xffffffffu, v, o);
    if ((threadIdx.x & 31) == 0 && v) atomicOr(&g_lo16_or, v);
}

// ---------------- amax |x| (dual dtype) ----------------
__global__ void amax_x_kernel(const void* __restrict__ xv) {
    const bool f32mode = (g_lo16_or == 0u);
    float m = 0.0f;
    if (f32mode) {
        const float4* p = reinterpret_cast<const float4*>(xv);
        const int n = (BATCH_M * DIM_K) / 4;
        for (int i = blockIdx.x * blockDim.x + threadIdx.x; i < n; i += gridDim.x * blockDim.x) {
            float4 v = p[i];
            m = fmaxf(m, fabsf(v.x)); m = fmaxf(m, fabsf(v.y));
            m = fmaxf(m, fabsf(v.z)); m = fmaxf(m, fabsf(v.w));
        }
    } else {
        const uint4* p = reinterpret_cast<const uint4*>(xv);
        const int n = (BATCH_M * DIM_K) / 8;
        for (int i = blockIdx.x * blockDim.x + threadIdx.x; i < n; i += gridDim.x * blockDim.x) {
            uint4 v = p[i];
            uint32_t ws[4] = {v.x, v.y, v.z, v.w};
            #pragma unroll
            for (int j = 0; j < 4; j++) {
                __nv_bfloat162 h2 = *reinterpret_cast<__nv_bfloat162*>(&ws[j]);
                m = fmaxf(m, fabsf(__bfloat162float(h2.x)));
                m = fmaxf(m, fabsf(__bfloat162float(h2.y)));
            }
        }
    }
    #pragma unroll
    for (int o = 16; o > 0; o >>= 1) m = fmaxf(m, __shfl_xor_sync(0xffffffffu, m, o));
    if ((threadIdx.x & 31) == 0) atomicMax(&g_amax_bits[0], __float_as_uint(m));
}

// ---------------- amax |w| (fp32) ----------------
__global__ void amax_w_kernel(const float* __restrict__ w) {
    const float4* p = reinterpret_cast<const float4*>(w);
    const int n = (DIM_N * DIM_K) / 4;
    float m = 0.0f;
    for (int i = blockIdx.x * blockDim.x + threadIdx.x; i < n; i += gridDim.x * blockDim.x) {
        float4 v = p[i];
        m = fmaxf(m, fabsf(v.x)); m = fmaxf(m, fabsf(v.y));
        m = fmaxf(m, fabsf(v.z)); m = fmaxf(m, fabsf(v.w));
    }
    #pragma unroll
    for (int o = 16; o > 0; o >>= 1) m = fmaxf(m, __shfl_xor_sync(0xffffffffu, m, o));
    if ((threadIdx.x & 31) == 0) atomicMax(&g_amax_bits[1], __float_as_uint(m));
}

// ---------------- quantize x -> e4m3 grid (stored as f16), dual dtype ----------------
__global__ void quant_x_kernel(const void* __restrict__ xv) {
    const bool f32mode = (g_lo16_or == 0u);
    const float amax = __uint_as_float(g_amax_bits[0]);
    const float scale = 448.0f / fmaxf(amax, 1e-12f);
    if (f32mode) {
        const float4* p = reinterpret_cast<const float4*>(xv);
        uint2* q = reinterpret_cast<uint2*>(g_qx_h);
        const int n = (BATCH_M * DIM_K) / 4;
        for (int i = blockIdx.x * blockDim.x + threadIdx.x; i < n; i += gridDim.x * blockDim.x) {
            float4 v = p[i];
            uint2 o;
            o.x = qpair_h2(v.x * scale, v.y * scale);
            o.y = qpair_h2(v.z * scale, v.w * scale);
            q[i] = o;
        }
    } else {
        const uint4* p = reinterpret_cast<const uint4*>(xv);
        uint4* q = reinterpret_cast<uint4*>(g_qx_h);
        const int n = (BATCH_M * DIM_K) / 8;
        for (int i = blockIdx.x * blockDim.x + threadIdx.x; i < n; i += gridDim.x * blockDim.x) {
            uint4 v = p[i];
            uint32_t ws[4] = {v.x, v.y, v.z, v.w};
            uint4 o;
            uint32_t* op = reinterpret_cast<uint32_t*>(&o);
            #pragma unroll
            for (int j = 0; j < 4; j++) {
                __nv_bfloat162 h2 = *reinterpret_cast<__nv_bfloat162*>(&ws[j]);
                op[j] = qpair_h2(__bfloat162float(h2.x) * scale,
                                 __bfloat162float(h2.y) * scale);
            }
            q[i] = o;
        }
    }
}

// ---------------- quantize w: fp32 -> e4m3 grid (stored as f16) ----------------
__global__ void quant_w_kernel(const float* __restrict__ w) {
    const float amax = __uint_as_float(g_amax_bits[1]);
    const float scale = 448.0f / fmaxf(amax, 1e-12f);
    const float4* p = reinterpret_cast<const float4*>(w);
    uint2* q = reinterpret_cast<uint2*>(g_qw_h);
    const int n = (DIM_N * DIM_K) / 4;
    for (int i = blockIdx.x * blockDim.x + threadIdx.x; i < n; i += gridDim.x * blockDim.x) {
        float4 v = p[i];
        uint2 o;
        o.x = qpair_h2(v.x * scale, v.y * scale);
        o.y = qpair_h2(v.z * scale, v.w * scale);
        q[i] = o;
    }
}

// ======================= GEMM: mma.sync m16n8k16 f16 =======================
// C[8192,4096] = qx @ qw^T, both K-major f16 (row.col TN).
// CTA 128x128x64(f16), 256 threads, warp tile 64x32, 3-stage cp.async.

#define BM 128
#define BN 128
#define BK 64                                    // f16 elements -> 128B per row
#define GSTAGES 3
#define K_ITERS (DIM_K / BK)                     // 64
#define A_TILE_B (BM * BK * 2)                   // 16384
#define STAGE_BYTES (2 * A_TILE_B)               // 32768 (A + B)
#define SMEM_GEMM (GSTAGES * STAGE_BYTES)        // 98304

// swizzle within a [rows][128B] tile: XOR 16B-chunk index (3 bits) with row&7
DEV_INLINE uint32_t swzh(uint32_t row, uint32_t byte) {
    return row * 128u + ((((byte >> 4) ^ (row & 7u)) << 4) | (byte & 15u));
}

DEV_INLINE void cp16(uint32_t dst, const void* src) {
    asm volatile("cp.async.cg.shared.global [%0], [%1], 16;" :: "r"(dst), "l"(src));
}
DEV_INLINE void cp_commit() { asm volatile("cp.async.commit_group;" ::: "memory"); }
DEV_INLINE void cp_wait1()  { asm volatile("cp.async.wait_group 1;" ::: "memory"); }
DEV_INLINE void cp_wait0()  { asm volatile("cp.async.wait_group 0;" ::: "memory"); }

DEV_INLINE uint32_t lds32(uint32_t addr) {
    uint32_t v;
    asm volatile("ld.shared.u32 %0, [%1];" : "=r"(v) : "r"(addr));
    return v;
}

DEV_INLINE void mma_f16(float* c, const uint32_t* a, const uint32_t* b) {
    asm volatile(
        "mma.sync.aligned.m16n8k16.row.col.f32.f16.f16.f32 "
        "{%0,%1,%2,%3}, {%4,%5,%6,%7}, {%8,%9}, {%0,%1,%2,%3};"
        : "+f"(c[0]), "+f"(c[1]), "+f"(c[2]), "+f"(c[3])
        : "r"(a[0]), "r"(a[1]), "r"(a[2]), "r"(a[3]), "r"(b[0]), "r"(b[1]));
}

__global__ void __launch_bounds__(256, 2)
gemm_f16_kernel(const float* __restrict__ bias, void* __restrict__ outv) {
    extern __shared__ __align__(128) char smem_raw[];
    const uint32_t smem0 = (uint32_t)__cvta_generic_to_shared(smem_raw);

    const int tid  = threadIdx.x;
    const int wid  = tid >> 5;
    const int lane = tid & 31;
    const int warpM = (wid & 1) * 64;   // 2 warps over M
    const int warpN = (wid >> 1) * 32;  // 4 warps over N
    const int g  = lane >> 2;           // fragment row group 0..7
    const int t4 = (lane & 3) * 4;      // fragment k-byte offset 0,4,8,12

    const int bx = blockIdx.x;   // N tile (32)
    const int by = blockIdx.y;   // M tile (64)
    const __half* gA = g_qx_h + (size_t)by * BM * DIM_K;
    const __half* gB = g_qw_h + (size_t)bx * BN * DIM_K;

    auto load_stage = [&](int s, int kb) {
        const uint32_t base = smem0 + (uint32_t)s * STAGE_BYTES;
        const __half* aSrc = gA + (size_t)kb * BK;
        #pragma unroll
        for (int i = 0; i < 4; i++) {
            int idx = i * 256 + tid;               // 0..1023
            uint32_t row = (uint32_t)(idx >> 3), c = (uint32_t)(idx & 7);
            cp16(base + row * 128u + ((c ^ (row & 7u)) << 4),
                 aSrc + (size_t)row * DIM_K + c * 8);
        }
        const uint32_t bbase = base + A_TILE_B;
        const __half* bSrc = gB + (size_t)kb * BK;
        #pragma unroll
        for (int i = 0; i < 4; i++) {
            int idx = i * 256 + tid;
            uint32_t row = (uint32_t)(idx >> 3), c = (uint32_t)(idx & 7);
            cp16(bbase + row * 128u + ((c ^ (row & 7u)) << 4),
                 bSrc + (size_t)row * DIM_K + c * 8);
        }
    };

    float acc[4][4][4];
    #pragma unroll
    for (int mi = 0; mi < 4; mi++)
        #pragma unroll
        for (int ni = 0; ni < 4; ni++)
            #pragma unroll
            for (int j = 0; j < 4; j++) acc[mi][ni][j] = 0.0f;

    // prologue: 2 stages in flight
    load_stage(0, 0); cp_commit();
    load_stage(1, 1); cp_commit();

    int sC = 0;       // stage holding chunk k
    int sL = 2;       // stage to load chunk k+2 into
    for (int k = 0; k < K_ITERS; k++) {
        cp_wait1();           // chunk-k group complete
        __syncthreads();      // all warps done reading the stage being refilled

        const int kn = k + 2;
        if (kn < K_ITERS) load_stage(sL, kn);
        cp_commit();          // exactly one group per iter (accounting)

        const uint32_t aBase = smem0 + (uint32_t)sC * STAGE_BYTES;
        const uint32_t bBase = aBase + A_TILE_B;

        #pragma unroll
        for (int ks = 0; ks < 4; ks++) {
            const uint32_t kb0 = (uint32_t)(ks * 32 + t4);   // k bytes for a0/a1,b0
            const uint32_t kb1 = kb0 + 16u;                  // k bytes for a2/a3,b1
            uint32_t af[4][4];
            uint32_t bf[4][2];
            #pragma unroll
            for (int mi = 0; mi < 4; mi++) {
                const uint32_t r0 = (uint32_t)(warpM + mi * 16 + g);
                af[mi][0] = lds32(aBase + swzh(r0,      kb0));
                af[mi][1] = lds32(aBase + swzh(r0 + 8u, kb0));
                af[mi][2] = lds32(aBase + swzh(r0,      kb1));
                af[mi][3] = lds32(aBase + swzh(r0 + 8u, kb1));
            }
            #pragma unroll
            for (int ni = 0; ni < 4; ni++) {
                const uint32_t rn = (uint32_t)(warpN + ni * 8 + g);
                bf[ni][0] = lds32(bBase + swzh(rn, kb0));
                bf[ni][1] = lds32(bBase + swzh(rn, kb1));
            }
            #pragma unroll
            for (int mi = 0; mi < 4; mi++)
                #pragma unroll
                for (int ni = 0; ni < 4; ni++)
                    mma_f16(acc[mi][ni], af[mi], bf[ni]);
        }

        sC = (sC == GSTAGES - 1) ? 0 : sC + 1;
        sL = (sL == GSTAGES - 1) ? 0 : sL + 1;
    }
    cp_wait0();  // drain trailing (possibly empty) groups

    // ---------------- epilogue: scale, bf16 bias add, dual-dtype store ------
    const float ax = __uint_as_float(g_amax_bits[0]);
    const float aw = __uint_as_float(g_amax_bits[1]);
    const float sc = (1.0f / (448.0f / fmaxf(ax, 1e-12f)))
                   * (1.0f / (448.0f / fmaxf(aw, 1e-12f)));
    const bool f32out = (g_lo16_or == 0u);

    const int colQ = (lane & 3) << 1;            // 0,2,4,6
    __nv_bfloat16 bb[4][2];
    #pragma unroll
    for (int ni = 0; ni < 4; ni++) {
        const int col = bx * BN + warpN + ni * 8 + colQ;
        const float2 bv = *reinterpret_cast<const float2*>(bias + col);
        bb[ni][0] = __float2bfloat16(bv.x);
        bb[ni][1] = __float2bfloat16(bv.y);
    }

    #pragma unroll
    for (int mi = 0; mi < 4; mi++) {
        const size_t row0 = (size_t)(by * BM + warpM + mi * 16 + (lane >> 2));
        #pragma unroll
        for (int ni = 0; ni < 4; ni++) {
            const size_t col = (size_t)(bx * BN + warpN + ni * 8 + colQ);
            __nv_bfloat16 v00 = __hadd(__float2bfloat16(acc[mi][ni][0] * sc), bb[ni][0]);
            __nv_bfloat16 v01 = __hadd(__float2bfloat16(acc[mi][ni][1] * sc), bb[ni][1]);
            __nv_bfloat16 v10 = __hadd(__float2bfloat16(acc[mi][ni][2] * sc), bb[ni][0]);
            __nv_bfloat16 v11 = __hadd(__float2bfloat16(acc[mi][ni][3] * sc), bb[ni][1]);
            if (f32out) {
                float* outp = reinterpret_cast<float*>(outv);
                *reinterpret_cast<float2*>(outp + row0 * DIM_N + col) =
                    make_float2(__bfloat162float(v00), __bfloat162float(v01));
                *reinterpret_cast<float2*>(outp + (row0 + 8) * DIM_N + col) =
                    make_float2(__bfloat162float(v10), __bfloat162float(v11));
            } else {
                __nv_bfloat16* outp = reinterpret_cast<__nv_bfloat16*>(outv);
                __nv_bfloat162 lo = __halves2bfloat162(v00, v01);
                __nv_bfloat162 hi = __halves2bfloat162(v10, v11);
                *reinterpret_cast<uint32_t*>(outp + row0 * DIM_N + col) =
                    *reinterpret_cast<uint32_t*>(&lo);
                *reinterpret_cast<uint32_t*>(outp + (row0 + 8) * DIM_N + col) =
                    *reinterpret_cast<uint32_t*>(&hi);
            }
        }
    }
}

// ---------------- launch ----------------
extern "C" void kernel_launch(void* const* d_in, const int* in_sizes, int n_in,
                              void* d_out, int out_size) {
    // input identification by element count (robust to metadata order)
    const void* x = nullptr;
    const float* w = nullptr;
    const float* bias = nullptr;
    for (int i = 0; i < n_in; i++) {
        if (in_sizes[i] == BATCH_M * DIM_K)      x    = d_in[i];
        else if (in_sizes[i] == DIM_N * DIM_K)   w    = (const float*)d_in[i];
        else if (in_sizes[i] == DIM_N)           bias = (const float*)d_in[i];
    }

    init_kernel<<<1, 32>>>();
    probe_kernel<<<1, 256>>>((const unsigned int*)x);
    amax_x_kernel<<<1024, 256>>>(x);
    amax_w_kernel<<<1024, 256>>>(w);
    quant_x_kernel<<<2048, 256>>>(x);
    quant_w_kernel<<<2048, 256>>>(w);

    cudaFuncSetAttribute(gemm_f16_kernel,
                         cudaFuncAttributeMaxDynamicSharedMemorySize, SMEM_GEMM);
    gemm_f16_kernel<<<dim3(DIM_N / BN, BATCH_M / BM, 1), 256, SMEM_GEMM>>>(bias, d_out);
}